// round 8
// baseline (speedup 1.0000x reference)
#include <cuda_runtime.h>
#include <cstdint>

// ImplicitFunction: hidden 64x64 layers via mma.sync.m16n8k32.s8 (int8 tensor
// path, 2x MAC density vs bf16 k16). Two-digit int8 quantization:
//   x ~= rmax/127 * (a1 + a2/254)   (per-row rmax, dynamic)
//   W ~= cmax/127 * (w1 + w2/254)   (per-col cmax, static, prep kernel)
// 3 MMAs per k32 tile: I1 += a1*w1 ; Imix += a1*w2 ; Imix += a2*w1.
// Dequant: y = (I1 + Imix/254) * rmax*cmax/16129, exact int32 accumulation.
// A-fragments for the next layer are built from D-layout outputs with
// in-warp shfl + prmt (4-lane groups), no smem staging, no mainloop syncs.

#define NT 256
#define TILE_M 128          // 8 warps * 16 rows, 2 CTAs/SM
#define NEG 0.2f
#define NLAYER 6

#define OFF_WF   0
#define WF_BYTES (NLAYER * 2 * 8 * 32 * 16)   // [l][kt][nt][lane] uint4 = 49152
#define OFF_CS   (OFF_WF + WF_BYTES)          // 6*64 f32: cmax*sh/16129
#define OFF_BH   (OFF_CS + 1536)
#define OFF_W0   (OFF_BH + 1536)
#define OFF_S0   (OFF_W0 + 768)
#define OFF_B0   (OFF_S0 + 256)
#define OFF_WO   (OFF_B0 + 256)
#define OFF_SOBO (OFF_WO + 256)
#define SMEM_BYTES (OFF_SOBO + 16)

__device__ __align__(16) uint4 g_wfrag[NLAYER * 2 * 8 * 32];
__device__ float g_colmax[NLAYER * 64];

static __device__ __forceinline__ float lrelu(float t) { return fmaxf(t, NEG * t); }

static __device__ __forceinline__ uint32_t pack_s8x4(int b0, int b1, int b2, int b3) {
    uint32_t r;
    int z = 0;
    asm("cvt.pack.sat.s8.s32.b32 %0, %1, %2, %3;" : "=r"(r) : "r"(b3), "r"(b2), "r"(z));
    asm("cvt.pack.sat.s8.s32.b32 %0, %1, %2, %3;" : "=r"(r) : "r"(b1), "r"(b0), "r"(r));
    return r;   // byte0=b0, byte1=b1, byte2=b2, byte3=b3
}

static __device__ __forceinline__ void mma_s8(int* c, const uint32_t* a,
                                              uint32_t b0, uint32_t b1) {
    asm volatile(
        "mma.sync.aligned.m16n8k32.row.col.s32.s8.s8.s32 "
        "{%0,%1,%2,%3}, {%4,%5,%6,%7}, {%8,%9}, {%0,%1,%2,%3};"
        : "+r"(c[0]), "+r"(c[1]), "+r"(c[2]), "+r"(c[3])
        : "r"(a[0]), "r"(a[1]), "r"(a[2]), "r"(a[3]), "r"(b0), "r"(b1));
}

// ---------------- prep: weight digits in B-fragment order ----------------
// B frag m16n8k32 col: b0 byte i = (k = 4*(lane%4)+i, n = lane/4); b1: k+16.
__global__ void prep_weights(const float* __restrict__ wh) {
    int t = blockIdx.x * blockDim.x + threadIdx.x;
    if (t >= NLAYER * 2 * 8 * 32) return;
    int lane = t & 31;
    int nt = (t >> 5) & 7;
    int kt = (t >> 8) & 1;
    int l = t >> 9;
    int n = nt * 8 + (lane >> 2);
    int tp = lane & 3;
    const float* W = wh + l * 4096;   // W[k][n] row-major

    float cm = 0.f;
    for (int k = 0; k < 64; k++) cm = fmaxf(cm, fabsf(W[k * 64 + n]));
    if (cm == 0.f) cm = 1.f;

    int d1[8], d2[8];
#pragma unroll
    for (int i = 0; i < 8; i++) {
        int k = kt * 32 + ((i < 4) ? (4 * tp + i) : (16 + 4 * tp + (i - 4)));
        float v = W[k * 64 + n] / cm * 127.f;
        int i1 = __float2int_rn(v);
        float r2 = v - (float)i1;
        int i2 = __float2int_rn(r2 * 254.f);
        d1[i] = i1; d2[i] = i2;
    }
    uint4 o;
    o.x = pack_s8x4(d1[0], d1[1], d1[2], d1[3]);
    o.y = pack_s8x4(d1[4], d1[5], d1[6], d1[7]);
    o.z = pack_s8x4(d2[0], d2[1], d2[2], d2[3]);
    o.w = pack_s8x4(d2[4], d2[5], d2[6], d2[7]);
    g_wfrag[((l * 2 + kt) * 8 + nt) * 32 + lane] = o;
    g_colmax[l * 64 + n] = cm;
}

// quantize o[nt][e] (e: 0,1 = row g cols even/odd; 2,3 = row g+8) -> digits
static __device__ __forceinline__ void quantize_rows(
    const float (&o)[8][4], int (&pk)[2][2][4], float& rmax0, float& rmax1)
{
    float m0 = 0.f, m1 = 0.f;
#pragma unroll
    for (int nt = 0; nt < 8; nt++) {
        m0 = fmaxf(m0, fmaxf(fabsf(o[nt][0]), fabsf(o[nt][1])));
        m1 = fmaxf(m1, fmaxf(fabsf(o[nt][2]), fabsf(o[nt][3])));
    }
    m0 = fmaxf(m0, __shfl_xor_sync(0xffffffffu, m0, 1));
    m0 = fmaxf(m0, __shfl_xor_sync(0xffffffffu, m0, 2));
    m1 = fmaxf(m1, __shfl_xor_sync(0xffffffffu, m1, 1));
    m1 = fmaxf(m1, __shfl_xor_sync(0xffffffffu, m1, 2));
    rmax0 = fmaxf(m0, 1e-20f);
    rmax1 = fmaxf(m1, 1e-20f);
    float inv0 = 127.f / rmax0;
    float inv1 = 127.f / rmax1;
#pragma unroll
    for (int j = 0; j < 4; j++) {
        int q1[2][4], q2[2][4];
#pragma unroll
        for (int h = 0; h < 2; h++) {
            int nt = 2 * j + h;
#pragma unroll
            for (int e = 0; e < 2; e++) {
                float inv = (e == 0) ? inv0 : inv1;
                float ta = o[nt][2 * e + 0] * inv;
                int a1 = __float2int_rn(ta);
                float ra = ta - (float)a1;
                int a2 = __float2int_rn(ra * 254.f);
                float tb = o[nt][2 * e + 1] * inv;
                int b1 = __float2int_rn(tb);
                float rb = tb - (float)b1;
                int b2 = __float2int_rn(rb * 254.f);
                q1[e][2 * h + 0] = a1; q1[e][2 * h + 1] = b1;
                q2[e][2 * h + 0] = a2; q2[e][2 * h + 1] = b2;
            }
        }
        pk[0][0][j] = (int)pack_s8x4(q1[0][0], q1[0][1], q1[0][2], q1[0][3]);
        pk[0][1][j] = (int)pack_s8x4(q2[0][0], q2[0][1], q2[0][2], q2[0][3]);
        pk[1][0][j] = (int)pack_s8x4(q1[1][0], q1[1][1], q1[1][2], q1[1][3]);
        pk[1][1][j] = (int)pack_s8x4(q2[1][0], q2[1][1], q2[1][2], q2[1][3]);
    }
}

__global__ __launch_bounds__(NT, 2)
void implicit_mlp_i8(const float* __restrict__ points,
                     const float* __restrict__ w0,
                     const float* __restrict__ s0,
                     const float* __restrict__ b0,
                     const float* __restrict__ sh,
                     const float* __restrict__ bh,
                     const float* __restrict__ wo,
                     const float* __restrict__ so,
                     const float* __restrict__ bo,
                     float* __restrict__ out,
                     int n, int ntiles)
{
    extern __shared__ __align__(16) unsigned char smem[];

    const int tid = threadIdx.x;
    const int wid = tid >> 5;
    const int lane = tid & 31;
    const int tig = lane & 3;
    const int grp = lane >> 2;
    const int cb = tig * 2;
    const int src1 = (lane & ~3) | ((tig & 1) << 1);   // owner lane pair base
    const uint32_t sel = (tig >> 1) ? 0x7632u : 0x5410u;

    {   // stage weights + params
        const uint4* gsrc = (const uint4*)g_wfrag;
        uint4* gdst = (uint4*)(smem + OFF_WF);
        for (int i = tid; i < WF_BYTES / 16; i += NT) gdst[i] = gsrc[i];
        float* cs = (float*)(smem + OFF_CS);
        for (int i = tid; i < NLAYER * 64; i += NT)
            cs[i] = g_colmax[i] * sh[i] * (1.f / 16129.f);
        float* d;
        d = (float*)(smem + OFF_BH); for (int i = tid; i < 384; i += NT) d[i] = bh[i];
        d = (float*)(smem + OFF_W0); for (int i = tid; i < 192; i += NT) d[i] = w0[i];
        d = (float*)(smem + OFF_S0); if (tid < 64) d[tid] = s0[tid];
        d = (float*)(smem + OFF_B0); if (tid < 64) d[tid] = b0[tid];
        d = (float*)(smem + OFF_WO); if (tid < 64) d[tid] = wo[tid];
        if (tid == 0) {
            ((float*)(smem + OFF_SOBO))[0] = so[0];
            ((float*)(smem + OFF_SOBO))[1] = bo[0];
        }
    }
    __syncthreads();

    const float* shm_cs = (const float*)(smem + OFF_CS);
    const float* shm_bh = (const float*)(smem + OFF_BH);
    const float* shm_w0 = (const float*)(smem + OFF_W0);
    const float* shm_s0 = (const float*)(smem + OFF_S0);
    const float* shm_b0 = (const float*)(smem + OFF_B0);
    const float* shm_wo = (const float*)(smem + OFF_WO);
    const float so_v = ((const float*)(smem + OFF_SOBO))[0];
    const float bo_v = ((const float*)(smem + OFF_SOBO))[1];
    const uint4* wf_sh = (const uint4*)(smem + OFF_WF);

    for (int tile = blockIdx.x; tile < ntiles; tile += gridDim.x) {
        const long long r0 = (long long)tile * TILE_M + wid * 16 + grp;
        const long long r1 = r0 + 8;

        int pk[2][2][4];      // [row g / g+8][digit][j: nt pair]
        float rmax0, rmax1;

        // ---- layer 0 (K=3) scalar, then quantize ----
        {
            float p0x = 0.f, p0y = 0.f, p0z = 0.f, p1x = 0.f, p1y = 0.f, p1z = 0.f;
            if (r0 < n) { p0x = points[r0*3+0]; p0y = points[r0*3+1]; p0z = points[r0*3+2]; }
            if (r1 < n) { p1x = points[r1*3+0]; p1y = points[r1*3+1]; p1z = points[r1*3+2]; }
            float o[8][4];
#pragma unroll
            for (int nt = 0; nt < 8; nt++) {
#pragma unroll
                for (int j = 0; j < 2; j++) {
                    int c = nt * 8 + cb + j;
                    float wa = shm_w0[c], wb = shm_w0[64 + c], wc = shm_w0[128 + c];
                    float sv = shm_s0[c], bv = shm_b0[c];
                    o[nt][j]     = lrelu(fmaf(fmaf(p0x, wa, fmaf(p0y, wb, p0z * wc)), sv, bv));
                    o[nt][2 + j] = lrelu(fmaf(fmaf(p1x, wa, fmaf(p1y, wb, p1z * wc)), sv, bv));
                }
            }
            quantize_rows(o, pk, rmax0, rmax1);
        }

        // ---- 6 hidden layers on int8 tensor cores ----
        float d0 = 0.f, d1 = 0.f;   // output-layer partial dots
#pragma unroll 1
        for (int l = 0; l < NLAYER; l++) {
            int I1[8][4], Imix[8][4];
#pragma unroll
            for (int nt = 0; nt < 8; nt++)
#pragma unroll
                for (int e = 0; e < 4; e++) { I1[nt][e] = 0; Imix[nt][e] = 0; }

            const uint4* wl = wf_sh + (l * 2) * 8 * 32 + lane;
#pragma unroll
            for (int kt = 0; kt < 2; kt++) {
                // A fragments from prev digits: shfl within 4-lane group + prmt
                uint32_t aD[2][4];
#pragma unroll
                for (int dg = 0; dg < 2; dg++) {
                    uint32_t p0a = __shfl_sync(0xffffffffu, (uint32_t)pk[0][dg][2*kt],     src1);
                    uint32_t p0b = __shfl_sync(0xffffffffu, (uint32_t)pk[0][dg][2*kt],     src1 + 1);
                    uint32_t p1a = __shfl_sync(0xffffffffu, (uint32_t)pk[1][dg][2*kt],     src1);
                    uint32_t p1b = __shfl_sync(0xffffffffu, (uint32_t)pk[1][dg][2*kt],     src1 + 1);
                    uint32_t q0a = __shfl_sync(0xffffffffu, (uint32_t)pk[0][dg][2*kt + 1], src1);
                    uint32_t q0b = __shfl_sync(0xffffffffu, (uint32_t)pk[0][dg][2*kt + 1], src1 + 1);
                    uint32_t q1a = __shfl_sync(0xffffffffu, (uint32_t)pk[1][dg][2*kt + 1], src1);
                    uint32_t q1b = __shfl_sync(0xffffffffu, (uint32_t)pk[1][dg][2*kt + 1], src1 + 1);
                    aD[dg][0] = __byte_perm(p0a, p0b, sel);
                    aD[dg][1] = __byte_perm(p1a, p1b, sel);
                    aD[dg][2] = __byte_perm(q0a, q0b, sel);
                    aD[dg][3] = __byte_perm(q1a, q1b, sel);
                }
#pragma unroll
                for (int nt = 0; nt < 8; nt++) {
                    uint4 w = wl[(kt * 8 + nt) * 32];
                    mma_s8(I1[nt],   aD[0], w.x, w.y);   // a1*w1
                    mma_s8(Imix[nt], aD[0], w.z, w.w);   // a1*w2
                    mma_s8(Imix[nt], aD[1], w.x, w.y);   // a2*w1
                }
            }

            // ---- dequant epilogue ----
            const float* csl = shm_cs + l * 64;
            const float* bl = shm_bh + l * 64;
            const float C254 = 1.f / 254.f;
            float o[8][4];
#pragma unroll
            for (int nt = 0; nt < 8; nt++) {
                int c0 = nt * 8 + cb;
                float cs0 = csl[c0], cs1 = csl[c0 + 1];
                float bb0 = bl[c0],  bb1 = bl[c0 + 1];
                float t00 = fmaf((float)Imix[nt][0], C254, (float)I1[nt][0]) * rmax0;
                float t01 = fmaf((float)Imix[nt][1], C254, (float)I1[nt][1]) * rmax0;
                float t10 = fmaf((float)Imix[nt][2], C254, (float)I1[nt][2]) * rmax1;
                float t11 = fmaf((float)Imix[nt][3], C254, (float)I1[nt][3]) * rmax1;
                o[nt][0] = lrelu(fmaf(t00, cs0, bb0));
                o[nt][1] = lrelu(fmaf(t01, cs1, bb1));
                o[nt][2] = lrelu(fmaf(t10, cs0, bb0));
                o[nt][3] = lrelu(fmaf(t11, cs1, bb1));
            }

            if (l < NLAYER - 1) {
                quantize_rows(o, pk, rmax0, rmax1);
            } else {
#pragma unroll
                for (int nt = 0; nt < 8; nt++) {
                    int c0 = nt * 8 + cb;
                    float w0v = shm_wo[c0], w1v = shm_wo[c0 + 1];
                    d0 = fmaf(o[nt][0], w0v, fmaf(o[nt][1], w1v, d0));
                    d1 = fmaf(o[nt][2], w0v, fmaf(o[nt][3], w1v, d1));
                }
            }
        }

        // ---- reduce across 4-lane group, store ----
        d0 += __shfl_xor_sync(0xffffffffu, d0, 1);
        d0 += __shfl_xor_sync(0xffffffffu, d0, 2);
        d1 += __shfl_xor_sync(0xffffffffu, d1, 1);
        d1 += __shfl_xor_sync(0xffffffffu, d1, 2);
        if (tig == 0) {
            if (r0 < n) out[r0] = fmaf(d0, so_v, bo_v);
            if (r1 < n) out[r1] = fmaf(d1, so_v, bo_v);
        }
    }
}

extern "C" void kernel_launch(void* const* d_in, const int* in_sizes, int n_in,
                              void* d_out, int out_size)
{
    const float* points = (const float*)d_in[0];
    const float* w0     = (const float*)d_in[1];
    const float* s0     = (const float*)d_in[2];
    const float* b0     = (const float*)d_in[3];
    const float* wh     = (const float*)d_in[4];
    const float* sh     = (const float*)d_in[5];
    const float* bh     = (const float*)d_in[6];
    const float* wo     = (const float*)d_in[7];
    const float* so     = (const float*)d_in[8];
    const float* bo     = (const float*)d_in[9];
    float* out = (float*)d_out;

    const int n = in_sizes[0] / 3;
    const int ntiles = (n + TILE_M - 1) / TILE_M;

    prep_weights<<<(NLAYER * 2 * 8 * 32 + 255) / 256, 256>>>(wh);

    int sms = 148;
    cudaDeviceGetAttribute(&sms, cudaDevAttrMultiProcessorCount, 0);
    cudaFuncSetAttribute(implicit_mlp_i8,
                         cudaFuncAttributeMaxDynamicSharedMemorySize, SMEM_BYTES);
    int grid = 2 * sms < ntiles ? 2 * sms : ntiles;

    implicit_mlp_i8<<<grid, NT, SMEM_BYTES>>>(
        points, w0, s0, b0, sh, bh, wo, so, bo, out, n, ntiles);
}

// round 9
// speedup vs baseline: 3.5768x; 3.5768x over previous
#include <cuda_runtime.h>
#include <cuda_fp16.h>
#include <cstdint>

// ImplicitFunction: hidden 64x64 layers via mma.sync fp16 m16n8k16 with a
// TWO-term static weight split (W = Whi + Wlo, fp16 digits, 22-bit effective)
// and dynamically range-scaled fp16 activations (per 8-row group rmax).
// Activation residual (~2^-12) is dropped -> 2 MMAs per k-tile instead of the
// bf16 kernel's 3. Dequant: y = acc * rmax (folded into scale/bias epilogue).

#define NT 256
#define TILE_M 256          // 8 warps * 32 rows, 1 CTA/SM
#define NEG 0.2f
#define NLAYER 6

#define OFF_WF   0
#define WF_BYTES (NLAYER * 8 * 4 * 32 * 16)   // [l][nt][kt][lane]{hi0,hi1,lo0,lo1}
#define OFF_SH   (OFF_WF + WF_BYTES)
#define OFF_BH   (OFF_SH + 1536)
#define OFF_W0   (OFF_BH + 1536)
#define OFF_S0   (OFF_W0 + 768)
#define OFF_B0   (OFF_S0 + 256)
#define OFF_WO   (OFF_B0 + 256)
#define OFF_SOBO (OFF_WO + 256)
#define SMEM_BYTES (OFF_SOBO + 16)

__device__ __align__(16) uint32_t g_wfrag[NLAYER * 8 * 4 * 32 * 4];

static __device__ __forceinline__ float lrelu(float t) { return fmaxf(t, NEG * t); }

static __device__ __forceinline__ uint32_t pack_h2(float a, float b) {
    __half2 h = __floats2half2_rn(a, b);   // a -> low, b -> high
    return *(uint32_t*)&h;
}

static __device__ __forceinline__ void mma_f16(float* c, const uint32_t* a,
                                               uint32_t b0, uint32_t b1) {
    asm volatile(
        "mma.sync.aligned.m16n8k16.row.col.f32.f16.f16.f32 "
        "{%0,%1,%2,%3}, {%4,%5,%6,%7}, {%8,%9}, {%0,%1,%2,%3};"
        : "+f"(c[0]), "+f"(c[1]), "+f"(c[2]), "+f"(c[3])
        : "r"(a[0]), "r"(a[1]), "r"(a[2]), "r"(a[3]), "r"(b0), "r"(b1));
}

// ---------------- prep: weights -> fp16 hi/lo digits in B-fragment order ----------------
__global__ void prep_weights(const float* __restrict__ wh) {
    int t = blockIdx.x * blockDim.x + threadIdx.x;
    if (t >= NLAYER * 8 * 4 * 32) return;
    int lane = t & 31;
    int kt = (t >> 5) & 3;
    int nt = (t >> 7) & 7;
    int l = t >> 10;
    int k0 = kt * 16 + (lane & 3) * 2;
    int nn = nt * 8 + (lane >> 2);
    const float* W = wh + l * 4096;       // W[k][n] row-major
    float w0 = W[k0 * 64 + nn];
    float w1 = W[(k0 + 1) * 64 + nn];
    float w2 = W[(k0 + 8) * 64 + nn];
    float w3 = W[(k0 + 9) * 64 + nn];

    __half h0 = __float2half_rn(w0), h1 = __float2half_rn(w1);
    __half h2 = __float2half_rn(w2), h3 = __float2half_rn(w3);
    float l0 = w0 - __half2float(h0), l1 = w1 - __half2float(h1);
    float l2 = w2 - __half2float(h2), l3 = w3 - __half2float(h3);

    uint4 o;
    __half2 p01 = __halves2half2(h0, h1);
    __half2 p23 = __halves2half2(h2, h3);
    o.x = *(uint32_t*)&p01;
    o.y = *(uint32_t*)&p23;
    o.z = pack_h2(l0, l1);
    o.w = pack_h2(l2, l3);
    ((uint4*)g_wfrag)[t] = o;
}

__global__ __launch_bounds__(NT, 1)
void implicit_mlp_f16(const float* __restrict__ points,
                      const float* __restrict__ w0,
                      const float* __restrict__ s0,
                      const float* __restrict__ b0,
                      const float* __restrict__ sh,
                      const float* __restrict__ bh,
                      const float* __restrict__ wo,
                      const float* __restrict__ so,
                      const float* __restrict__ bo,
                      float* __restrict__ out,
                      int n, int ntiles)
{
    extern __shared__ __align__(16) unsigned char smem[];

    const int tid = threadIdx.x;
    const int wid = tid >> 5;
    const int lane = tid & 31;
    const int tig = lane & 3;
    const int grp = lane >> 2;
    const int cb = tig * 2;

    {
        const uint4* gsrc = (const uint4*)g_wfrag;
        uint4* gdst = (uint4*)(smem + OFF_WF);
        for (int i = tid; i < WF_BYTES / 16; i += NT) gdst[i] = gsrc[i];
        float* d;
        d = (float*)(smem + OFF_SH); for (int i = tid; i < 384; i += NT) d[i] = sh[i];
        d = (float*)(smem + OFF_BH); for (int i = tid; i < 384; i += NT) d[i] = bh[i];
        d = (float*)(smem + OFF_W0); for (int i = tid; i < 192; i += NT) d[i] = w0[i];
        d = (float*)(smem + OFF_S0); if (tid < 64) d[tid] = s0[tid];
        d = (float*)(smem + OFF_B0); if (tid < 64) d[tid] = b0[tid];
        d = (float*)(smem + OFF_WO); if (tid < 64) d[tid] = wo[tid];
        if (tid == 0) {
            ((float*)(smem + OFF_SOBO))[0] = so[0];
            ((float*)(smem + OFF_SOBO))[1] = bo[0];
        }
    }
    __syncthreads();

    const float* shm_sh = (const float*)(smem + OFF_SH);
    const float* shm_bh = (const float*)(smem + OFF_BH);
    const float* shm_w0 = (const float*)(smem + OFF_W0);
    const float* shm_s0 = (const float*)(smem + OFF_S0);
    const float* shm_b0 = (const float*)(smem + OFF_B0);
    const float* shm_wo = (const float*)(smem + OFF_WO);
    const float so_v = ((const float*)(smem + OFF_SOBO))[0];
    const float bo_v = ((const float*)(smem + OFF_SOBO))[1];
    const uint4* wf_sh = (const uint4*)(smem + OFF_WF);

    for (int tile = blockIdx.x; tile < ntiles; tile += gridDim.x) {
        const long long rowbase = (long long)tile * TILE_M + wid * 32;

        float acc[2][8][4];          // activations / accumulators (fp32)
        uint32_t A[2][4][4];         // fp16 A fragments (scaled)
        float rm[2][2];              // dequant scales [mt][rowhalf]

        // ---- layer 0 (K=3) scalar into acc ----
#pragma unroll
        for (int mt = 0; mt < 2; mt++) {
            const long long r0 = rowbase + mt * 16 + grp;
            const long long r1 = r0 + 8;
            float p0x = 0.f, p0y = 0.f, p0z = 0.f, p1x = 0.f, p1y = 0.f, p1z = 0.f;
            if (r0 < n) { p0x = points[r0*3+0]; p0y = points[r0*3+1]; p0z = points[r0*3+2]; }
            if (r1 < n) { p1x = points[r1*3+0]; p1y = points[r1*3+1]; p1z = points[r1*3+2]; }
#pragma unroll
            for (int nt = 0; nt < 8; nt++) {
#pragma unroll
                for (int j = 0; j < 2; j++) {
                    int c = nt * 8 + cb + j;
                    float wa = shm_w0[c], wb = shm_w0[64 + c], wc = shm_w0[128 + c];
                    float sv = shm_s0[c], bv = shm_b0[c];
                    acc[mt][nt][j]     = lrelu(fmaf(fmaf(p0x, wa, fmaf(p0y, wb, p0z * wc)), sv, bv));
                    acc[mt][nt][2 + j] = lrelu(fmaf(fmaf(p1x, wa, fmaf(p1y, wb, p1z * wc)), sv, bv));
                }
            }
        }

        // ---- 6 hidden layers ----
#pragma unroll
        for (int l = 0; l < NLAYER; l++) {
            // quantize: per (mt, rowhalf) scale, pack fp16 A fragments
#pragma unroll
            for (int mt = 0; mt < 2; mt++) {
                float m0 = 0.f, m1 = 0.f;
#pragma unroll
                for (int nt = 0; nt < 8; nt++) {
                    m0 = fmaxf(m0, fmaxf(fabsf(acc[mt][nt][0]), fabsf(acc[mt][nt][1])));
                    m1 = fmaxf(m1, fmaxf(fabsf(acc[mt][nt][2]), fabsf(acc[mt][nt][3])));
                }
                m0 = fmaxf(m0, __shfl_xor_sync(0xffffffffu, m0, 1));
                m0 = fmaxf(m0, __shfl_xor_sync(0xffffffffu, m0, 2));
                m1 = fmaxf(m1, __shfl_xor_sync(0xffffffffu, m1, 1));
                m1 = fmaxf(m1, __shfl_xor_sync(0xffffffffu, m1, 2));
                m0 = fmaxf(m0, 1e-30f);
                m1 = fmaxf(m1, 1e-30f);
                rm[mt][0] = m0;
                rm[mt][1] = m1;
                float inv0 = 1.f / m0, inv1 = 1.f / m1;
#pragma unroll
                for (int kt = 0; kt < 4; kt++) {
                    A[mt][kt][0] = pack_h2(acc[mt][2*kt][0]   * inv0, acc[mt][2*kt][1]   * inv0);
                    A[mt][kt][1] = pack_h2(acc[mt][2*kt][2]   * inv1, acc[mt][2*kt][3]   * inv1);
                    A[mt][kt][2] = pack_h2(acc[mt][2*kt+1][0] * inv0, acc[mt][2*kt+1][1] * inv0);
                    A[mt][kt][3] = pack_h2(acc[mt][2*kt+1][2] * inv1, acc[mt][2*kt+1][3] * inv1);
                }
            }

            // MMA: 2 passes (Whi, Wlo), 16 independent MMAs per pass
#pragma unroll
            for (int mt = 0; mt < 2; mt++)
#pragma unroll
                for (int nt = 0; nt < 8; nt++)
#pragma unroll
                    for (int e = 0; e < 4; e++) acc[mt][nt][e] = 0.f;

            const uint4* wl = wf_sh + l * 1024 + lane;
#pragma unroll
            for (int kt = 0; kt < 4; kt++) {
                uint4 wf[8];
#pragma unroll
                for (int nt = 0; nt < 8; nt++) wf[nt] = wl[(nt * 4 + kt) * 32];
#pragma unroll
                for (int nt = 0; nt < 8; nt++) {
                    mma_f16(acc[0][nt], A[0][kt], wf[nt].x, wf[nt].y);   // W hi
                    mma_f16(acc[1][nt], A[1][kt], wf[nt].x, wf[nt].y);
                }
#pragma unroll
                for (int nt = 0; nt < 8; nt++) {
                    mma_f16(acc[0][nt], A[0][kt], wf[nt].z, wf[nt].w);   // W lo
                    mma_f16(acc[1][nt], A[1][kt], wf[nt].z, wf[nt].w);
                }
            }

            // dequant + scale/bias + lrelu (or fused output tail)
            const float* sl = shm_sh + l * 64;
            const float* bl = shm_bh + l * 64;
            if (l < NLAYER - 1) {
#pragma unroll
                for (int mt = 0; mt < 2; mt++) {
                    float r0v = rm[mt][0], r1v = rm[mt][1];
#pragma unroll
                    for (int nt = 0; nt < 8; nt++) {
                        int c0 = nt * 8 + cb;
                        float s0v = sl[c0], s1v = sl[c0 + 1];
                        float b0v = bl[c0], b1v = bl[c0 + 1];
                        acc[mt][nt][0] = lrelu(fmaf(acc[mt][nt][0] * r0v, s0v, b0v));
                        acc[mt][nt][1] = lrelu(fmaf(acc[mt][nt][1] * r0v, s1v, b1v));
                        acc[mt][nt][2] = lrelu(fmaf(acc[mt][nt][2] * r1v, s0v, b0v));
                        acc[mt][nt][3] = lrelu(fmaf(acc[mt][nt][3] * r1v, s1v, b1v));
                    }
                }
            } else {
#pragma unroll
                for (int mt = 0; mt < 2; mt++) {
                    float r0v = rm[mt][0], r1v = rm[mt][1];
                    float d0 = 0.f, d1 = 0.f;
#pragma unroll
                    for (int nt = 0; nt < 8; nt++) {
                        int c0 = nt * 8 + cb;
                        float s0v = sl[c0], s1v = sl[c0 + 1];
                        float b0v = bl[c0], b1v = bl[c0 + 1];
                        float w0v = shm_wo[c0], w1v = shm_wo[c0 + 1];
                        d0 = fmaf(lrelu(fmaf(acc[mt][nt][0] * r0v, s0v, b0v)), w0v, d0);
                        d0 = fmaf(lrelu(fmaf(acc[mt][nt][1] * r0v, s1v, b1v)), w1v, d0);
                        d1 = fmaf(lrelu(fmaf(acc[mt][nt][2] * r1v, s0v, b0v)), w0v, d1);
                        d1 = fmaf(lrelu(fmaf(acc[mt][nt][3] * r1v, s1v, b1v)), w1v, d1);
                    }
                    d0 += __shfl_xor_sync(0xffffffffu, d0, 1);
                    d0 += __shfl_xor_sync(0xffffffffu, d0, 2);
                    d1 += __shfl_xor_sync(0xffffffffu, d1, 1);
                    d1 += __shfl_xor_sync(0xffffffffu, d1, 2);
                    if (tig == 0) {
                        long long r0 = rowbase + mt * 16 + grp;
                        long long r1 = r0 + 8;
                        if (r0 < n) out[r0] = fmaf(d0, so_v, bo_v);
                        if (r1 < n) out[r1] = fmaf(d1, so_v, bo_v);
                    }
                }
            }
        }
    }
}

extern "C" void kernel_launch(void* const* d_in, const int* in_sizes, int n_in,
                              void* d_out, int out_size)
{
    const float* points = (const float*)d_in[0];
    const float* w0     = (const float*)d_in[1];
    const float* s0     = (const float*)d_in[2];
    const float* b0     = (const float*)d_in[3];
    const float* wh     = (const float*)d_in[4];
    const float* sh     = (const float*)d_in[5];
    const float* bh     = (const float*)d_in[6];
    const float* wo     = (const float*)d_in[7];
    const float* so     = (const float*)d_in[8];
    const float* bo     = (const float*)d_in[9];
    float* out = (float*)d_out;

    const int n = in_sizes[0] / 3;
    const int ntiles = (n + TILE_M - 1) / TILE_M;

    prep_weights<<<(NLAYER * 8 * 4 * 32 + 255) / 256, 256>>>(wh);

    int sms = 148;
    cudaDeviceGetAttribute(&sms, cudaDevAttrMultiProcessorCount, 0);
    cudaFuncSetAttribute(implicit_mlp_f16,
                         cudaFuncAttributeMaxDynamicSharedMemorySize, SMEM_BYTES);
    int grid = sms < ntiles ? sms : ntiles;

    implicit_mlp_f16<<<grid, NT, SMEM_BYTES>>>(
        points, w0, s0, b0, sh, bh, wo, so, bo, out, n, ntiles);
}